// round 16
// baseline (speedup 1.0000x reference)
#include <cuda_runtime.h>
#include <math.h>

#define HID 32
#define MAXN 10240
#define MAXSEF 1100000

// device scratch (no allocs allowed)
__device__ __align__(16) float g_A[2][MAXN * HID];  // z @ M_w[0:32], dbl-buffered
__device__ __align__(16) int2 g_pair[MAXSEF];       // (src, ef bits) [n][k], padded
__device__ float g_blockmax[8 * 1024];
__device__ volatile unsigned g_gen;                 // barrier generation
__device__ unsigned g_cnt;                          // barrier arrival count

// ---------------------------------------------------------------------------
// Software grid barrier (all blocks resident by construction).
// ---------------------------------------------------------------------------
__device__ __forceinline__ void grid_sync_dev() {
    __threadfence();
    __syncthreads();
    if (threadIdx.x == 0) {
        unsigned gen = g_gen;
        if (atomicAdd(&g_cnt, 1u) == gridDim.x - 1u) {
            g_cnt = 0u;
            __threadfence();
            g_gen = gen + 1u;
        } else {
            while (g_gen == gen) __nanosleep(32);
        }
    }
    __syncthreads();
}

// ---------------------------------------------------------------------------
// Persistent fused kernel: init + all T-1 steps + finalize. 8 warps,
// 2 nodes/warp, 16 nodes/block, grid ceil(N/16) (all resident: lb(256,5)).
// Step 0 gathers edge features from edges_mat on the fly (MLP-4 pipelined
// random DRAM reads) and caches (src, ef) into g_pair for steps >=1.
// z and Bc live in registers across steps.
// ---------------------------------------------------------------------------
__global__ void __launch_bounds__(256, 5) k_all(
        const float* __restrict__ states0, const float* __restrict__ pri,
        const float* __restrict__ edges,  const int* __restrict__ src,
        const float* __restrict__ encw, const float* __restrict__ encb,
        const float* __restrict__ Mw,   const float* __restrict__ Mb,
        const float* __restrict__ Uw,   const float* __restrict__ Ub,
        const float* __restrict__ dnw,  const float* __restrict__ dnb,
        const float* __restrict__ duw,  const float* __restrict__ dub,
        const float* __restrict__ termw,const float* __restrict__ termb,
        float* __restrict__ out, int N, int T, int KS8, int Kc, int Erem) {
    __shared__ float s_encw[34 * HID];
    __shared__ float s_Uw[64 * HID];
    __shared__ float s_Mw[64 * HID];
    __shared__ float s_dnw[64];
    __shared__ float s_duw[65];
    __shared__ float s_termw[HID];
    __shared__ __align__(16) float s_um[8][64];
    __shared__ __align__(8) float s_zs[HID][18];
    __shared__ __align__(8) float s_us[HID][18];
    __shared__ float s_red[8];
    __shared__ float s_fin[256];

    int tid = threadIdx.x;
    for (int i = tid; i < 34 * HID; i += 256) s_encw[i] = encw[i];
    for (int i = tid; i < 64 * HID; i += 256) s_Mw[i] = Mw[i];
    for (int i = tid; i < 64 * HID; i += 256) s_Uw[i] = Uw[i];
    if (tid < 64) s_dnw[tid] = dnw[tid];
    if (tid < 65) s_duw[tid] = duw[tid];
    if (tid < HID) s_termw[tid] = termw[tid];
    __syncthreads();

    int w = tid >> 5, j = tid & 31, qb = w * 2;
    int n0 = blockIdx.x * 16 + qb;
    bool active = (n0 < N);
    int g = j >> 3, c4 = (j & 7) << 2;      // lane group, col base
    bool gl = ((j & 7) == 0);               // group leader lane
    const float4 fw4 = *(const float4*)(Mw + 64 * HID + c4);

    float z0 = 0.f, z1 = 0.f, bc0 = 0.f, bc1 = 0.f;

    // ---------------- init: z0/A0/Bc0 from states[0], preds[0] --------------
    if (active) {
        const float2 st2 = *(const float2*)(states0 + n0);
        const float2 p2  = *(const float2*)(pri + n0);
        float eb = __ldg(encb + j);
        float ew0 = s_encw[j], ew33 = s_encw[33 * HID + j];
        z0 = fmaf(st2.x, ew0, fmaf(p2.x, ew33, eb));
        z1 = fmaf(st2.y, ew0, fmaf(p2.y, ew33, eb));
        if (j < 2) out[n0 + j] = (j == 0) ? st2.x : st2.y;
        s_zs[j][qb + 0] = z0; s_zs[j][qb + 1] = z1;
        __syncwarp();
        float A0 = 0, A1 = 0, B0 = 0, B1 = 0;
        #pragma unroll
        for (int i = 0; i < HID; i++) {
            float wa = s_Mw[i * HID + j], wb = s_Mw[(HID + i) * HID + j];
            float2 zq = *(const float2*)&s_zs[i][qb];
            A0 = fmaf(zq.x, wa, A0); B0 = fmaf(zq.x, wb, B0);
            A1 = fmaf(zq.y, wa, A1); B1 = fmaf(zq.y, wb, B1);
        }
        float mb = __ldg(Mb + j);
        int r = n0 * HID + j;
        g_A[0][r] = A0; g_A[0][r + HID] = A1;
        bc0 = B0 + mb; bc1 = B1 + mb;
    }
    grid_sync_dev();

    // ---------------- T-1 fused steps ---------------------------------------
    for (int t = 0; t < T - 1; t++) {
        bool lastStep = (t == T - 2);
        float locmax = -INFINITY;

        if (active) {
            const float* __restrict__ Aold = g_A[t & 1];
            #pragma unroll
            for (int qi = 0; qi < 2; qi++) {
                int n = n0 + qi;
                float mx = -INFINITY, my = -INFINITY, mz = -INFINITY, mw2 = -INFINITY;
                if (t == 0) {
                    // fused ef gather, MLP-4: 4 src loads, then 4 independent
                    // DRAM gathers in flight, then 4 A rows. Cache into g_pair.
                    int kn = Kc + (n < Erem ? 1 : 0);
                    long base = (long)n * KS8;
                    int k = 0;
                    for (; k + 16 <= KS8; k += 16) {
                        int k0 = k + g, k1 = k + 4 + g, k2 = k + 8 + g, k3 = k + 12 + g;
                        int e0 = (k0 < kn) ? k0 * N + n : n;
                        int e1 = (k1 < kn) ? k1 * N + n : n;
                        int e2 = (k2 < kn) ? k2 * N + n : n;
                        int e3 = (k3 < kn) ? k3 * N + n : n;
                        int s0 = __ldg(src + e0);
                        int s1 = __ldg(src + e1);
                        int s2 = __ldg(src + e2);
                        int s3 = __ldg(src + e3);
                        float f0 = __ldcs(edges + (long)s0 * N + n);
                        float f1 = __ldcs(edges + (long)s1 * N + n);
                        float f2 = __ldcs(edges + (long)s2 * N + n);
                        float f3 = __ldcs(edges + (long)s3 * N + n);
                        float4 a0 = __ldg((const float4*)(Aold + (s0 << 5) + c4));
                        float4 a1 = __ldg((const float4*)(Aold + (s1 << 5) + c4));
                        float4 a2 = __ldg((const float4*)(Aold + (s2 << 5) + c4));
                        float4 a3 = __ldg((const float4*)(Aold + (s3 << 5) + c4));
                        if (gl) {
                            g_pair[base + k0] = make_int2(s0, __float_as_int(f0));
                            g_pair[base + k1] = make_int2(s1, __float_as_int(f1));
                            g_pair[base + k2] = make_int2(s2, __float_as_int(f2));
                            g_pair[base + k3] = make_int2(s3, __float_as_int(f3));
                        }
                        mx  = fmaxf(mx,  fmaf(f0, fw4.x, a0.x));
                        my  = fmaxf(my,  fmaf(f0, fw4.y, a0.y));
                        mz  = fmaxf(mz,  fmaf(f0, fw4.z, a0.z));
                        mw2 = fmaxf(mw2, fmaf(f0, fw4.w, a0.w));
                        mx  = fmaxf(mx,  fmaf(f1, fw4.x, a1.x));
                        my  = fmaxf(my,  fmaf(f1, fw4.y, a1.y));
                        mz  = fmaxf(mz,  fmaf(f1, fw4.z, a1.z));
                        mw2 = fmaxf(mw2, fmaf(f1, fw4.w, a1.w));
                        mx  = fmaxf(mx,  fmaf(f2, fw4.x, a2.x));
                        my  = fmaxf(my,  fmaf(f2, fw4.y, a2.y));
                        mz  = fmaxf(mz,  fmaf(f2, fw4.z, a2.z));
                        mw2 = fmaxf(mw2, fmaf(f2, fw4.w, a2.w));
                        mx  = fmaxf(mx,  fmaf(f3, fw4.x, a3.x));
                        my  = fmaxf(my,  fmaf(f3, fw4.y, a3.y));
                        mz  = fmaxf(mz,  fmaf(f3, fw4.z, a3.z));
                        mw2 = fmaxf(mw2, fmaf(f3, fw4.w, a3.w));
                    }
                    for (; k < KS8; k += 8) {   // 8-edge tail
                        int k0 = k + g, k1 = k + 4 + g;
                        int e0 = (k0 < kn) ? k0 * N + n : n;
                        int e1 = (k1 < kn) ? k1 * N + n : n;
                        int s0 = __ldg(src + e0);
                        int s1 = __ldg(src + e1);
                        float f0 = __ldcs(edges + (long)s0 * N + n);
                        float f1 = __ldcs(edges + (long)s1 * N + n);
                        float4 a0 = __ldg((const float4*)(Aold + (s0 << 5) + c4));
                        float4 a1 = __ldg((const float4*)(Aold + (s1 << 5) + c4));
                        if (gl) {
                            g_pair[base + k0] = make_int2(s0, __float_as_int(f0));
                            g_pair[base + k1] = make_int2(s1, __float_as_int(f1));
                        }
                        mx  = fmaxf(mx,  fmaf(f0, fw4.x, a0.x));
                        my  = fmaxf(my,  fmaf(f0, fw4.y, a0.y));
                        mz  = fmaxf(mz,  fmaf(f0, fw4.z, a0.z));
                        mw2 = fmaxf(mw2, fmaf(f0, fw4.w, a0.w));
                        mx  = fmaxf(mx,  fmaf(f1, fw4.x, a1.x));
                        my  = fmaxf(my,  fmaf(f1, fw4.y, a1.y));
                        mz  = fmaxf(mz,  fmaf(f1, fw4.z, a1.z));
                        mw2 = fmaxf(mw2, fmaf(f1, fw4.w, a1.w));
                    }
                } else {
                    const int2* __restrict__ pp = g_pair + (long)n * KS8 + g;
                    for (int k = 0; k < KS8; k += 8) {
                        int2 q0 = __ldg(pp + k);
                        int2 q1 = __ldg(pp + k + 4);
                        float4 a0 = __ldg((const float4*)(Aold + (q0.x << 5) + c4));
                        float4 a1 = __ldg((const float4*)(Aold + (q1.x << 5) + c4));
                        float f0 = __int_as_float(q0.y);
                        float f1 = __int_as_float(q1.y);
                        mx  = fmaxf(mx,  fmaf(f0, fw4.x, a0.x));
                        my  = fmaxf(my,  fmaf(f0, fw4.y, a0.y));
                        mz  = fmaxf(mz,  fmaf(f0, fw4.z, a0.z));
                        mw2 = fmaxf(mw2, fmaf(f0, fw4.w, a0.w));
                        mx  = fmaxf(mx,  fmaf(f1, fw4.x, a1.x));
                        my  = fmaxf(my,  fmaf(f1, fw4.y, a1.y));
                        mz  = fmaxf(mz,  fmaf(f1, fw4.z, a1.z));
                        mw2 = fmaxf(mw2, fmaf(f1, fw4.w, a1.w));
                    }
                }
                mx  = fmaxf(mx,  __shfl_xor_sync(0xffffffffu, mx, 8));
                my  = fmaxf(my,  __shfl_xor_sync(0xffffffffu, my, 8));
                mz  = fmaxf(mz,  __shfl_xor_sync(0xffffffffu, mz, 8));
                mw2 = fmaxf(mw2, __shfl_xor_sync(0xffffffffu, mw2, 8));
                mx  = fmaxf(mx,  __shfl_xor_sync(0xffffffffu, mx, 16));
                my  = fmaxf(my,  __shfl_xor_sync(0xffffffffu, my, 16));
                mz  = fmaxf(mz,  __shfl_xor_sync(0xffffffffu, mz, 16));
                mw2 = fmaxf(mw2, __shfl_xor_sync(0xffffffffu, mw2, 16));
                if (g == 0)
                    *(float4*)&s_um[w][qi * 32 + c4] = make_float4(mx, my, mz, mw2);
            }
            __syncwarp();

            // ---------------- node phase (z, Bc in registers) ---------------
            float u0 = bc0 + s_um[w][j];
            float u1 = bc1 + s_um[w][32 + j];
            s_zs[j][qb + 0] = z0; s_zs[j][qb + 1] = z1;
            s_us[j][qb + 0] = u0; s_us[j][qb + 1] = u1;
            __syncwarp();
            float ub = __ldg(Ub + j);
            float nh0 = ub, nh1 = ub;
            #pragma unroll
            for (int i = 0; i < HID; i++) {
                float wz = s_Uw[i * HID + j], wu = s_Uw[(HID + i) * HID + j];
                float2 zq = *(const float2*)&s_zs[i][qb];
                float2 uq = *(const float2*)&s_us[i][qb];
                nh0 = fmaf(zq.x, wz, nh0); nh0 = fmaf(uq.x, wu, nh0);
                nh1 = fmaf(zq.y, wz, nh1); nh1 = fmaf(uq.y, wu, nh1);
            }
            float tw = s_termw[j], d1 = s_dnw[j], d2 = s_dnw[HID + j];
            float e1 = s_duw[j], e2 = s_duw[HID + j];
            float l0 = nh0 * tw, l1 = nh1 * tw;
            float qd0 = fmaf(nh0, d1, z0 * d2), qd1 = fmaf(nh1, d1, z1 * d2);
            float rd0 = fmaf(nh0, e1, z0 * e2), rd1 = fmaf(nh1, e1, z1 * e2);
            #pragma unroll
            for (int o = 16; o; o >>= 1) {
                l0  += __shfl_xor_sync(0xffffffffu, l0, o);
                l1  += __shfl_xor_sync(0xffffffffu, l1, o);
                qd0 += __shfl_xor_sync(0xffffffffu, qd0, o);
                qd1 += __shfl_xor_sync(0xffffffffu, qd1, o);
                rd0 += __shfl_xor_sync(0xffffffffu, rd0, o);
                rd1 += __shfl_xor_sync(0xffffffffu, rd1, o);
            }
            locmax = fmaxf(l0, l1) + __ldg(termb);
            float db = __ldg(dnb), du0 = __ldg(dub), dw64 = s_duw[64];
            float nn0 = qd0 + db, nn1 = qd1 + db;
            float ns0 = fmaf(nn0, dw64, rd0 + du0);
            float ns1 = fmaf(nn1, dw64, rd1 + du0);
            if (j < 2) {
                float nsv = (j == 0) ? ns0 : ns1;
                float nnv = (j == 0) ? nn0 : nn1;
                out[(t + 1) * N + n0 + j] = nsv;                  // preds
                out[T * N + T + (n0 + j) * (T - 1) + t] = nnv;    // preds_nextnode
            }
            if (!lastStep) {
                s_zs[j][qb + 0] = nh0; s_zs[j][qb + 1] = nh1;
                __syncwarp();
                const float2 p2 = *(const float2*)(pri + n0);
                float eb = __ldg(encb + j);
                float ew0 = s_encw[j], ew33 = s_encw[33 * HID + j];
                float zn0 = fmaf(ns0, ew0, fmaf(p2.x, ew33, eb));
                float zn1 = fmaf(ns1, ew0, fmaf(p2.y, ew33, eb));
                #pragma unroll
                for (int i = 0; i < HID; i++) {
                    float we = s_encw[(1 + i) * HID + j];
                    float2 hq = *(const float2*)&s_zs[i][qb];
                    zn0 = fmaf(hq.x, we, zn0); zn1 = fmaf(hq.y, we, zn1);
                }
                s_us[j][qb + 0] = zn0; s_us[j][qb + 1] = zn1;
                __syncwarp();
                float A0 = 0, A1 = 0, B0 = 0, B1 = 0;
                #pragma unroll
                for (int i = 0; i < HID; i++) {
                    float wa = s_Mw[i * HID + j], wb = s_Mw[(HID + i) * HID + j];
                    float2 zq = *(const float2*)&s_us[i][qb];
                    A0 = fmaf(zq.x, wa, A0); B0 = fmaf(zq.x, wb, B0);
                    A1 = fmaf(zq.y, wa, A1); B1 = fmaf(zq.y, wb, B1);
                }
                float mb = __ldg(Mb + j);
                float* __restrict__ Anew = g_A[(t & 1) ^ 1];
                int r = n0 * HID + j;
                Anew[r] = A0; Anew[r + HID] = A1;
                z0 = zn0; z1 = zn1;
                bc0 = B0 + mb; bc1 = B1 + mb;
            }
        }

        if (j == 0) s_red[w] = active ? locmax : -INFINITY;
        __syncthreads();
        if (tid == 0) {
            float m = -INFINITY;
            #pragma unroll
            for (int ww = 0; ww < 8; ww++) m = fmaxf(m, s_red[ww]);
            g_blockmax[t * 1024 + blockIdx.x] = m;
        }
        if (!lastStep) grid_sync_dev();
    }

    // ---------------- finalize (folded k_final) -----------------------------
    grid_sync_dev();
    if (blockIdx.x < (unsigned)(T - 1)) {
        int t = blockIdx.x;
        float m = -INFINITY;
        for (int b = tid; b < gridDim.x; b += 256)
            m = fmaxf(m, g_blockmax[t * 1024 + b]);
        s_fin[tid] = m;
        __syncthreads();
        for (int s = 128; s; s >>= 1) {
            if (tid < s) s_fin[tid] = fmaxf(s_fin[tid], s_fin[tid + s]);
            __syncthreads();
        }
        if (tid == 0) {
            float v = s_fin[0];
            out[T * N + 1 + t] = 1.0f / (1.0f + expf(-v));
            if (t == 0) out[T * N] = 0.0f;
        }
    }
}

// ---------------------------------------------------------------------------
extern "C" void kernel_launch(void* const* d_in, const int* in_sizes, int n_in,
                              void* d_out, int out_size) {
    const float* states   = (const float*)d_in[0];
    const float* priority = (const float*)d_in[1];
    const float* edges    = (const float*)d_in[2];
    const int*   src      = (const int*)d_in[3];
    const float* enc_w    = (const float*)d_in[5];
    const float* enc_b    = (const float*)d_in[6];
    const float* M_w      = (const float*)d_in[7];
    const float* M_b      = (const float*)d_in[8];
    const float* U_w      = (const float*)d_in[9];
    const float* U_b      = (const float*)d_in[10];
    const float* dn_w     = (const float*)d_in[11];
    const float* dn_b     = (const float*)d_in[12];
    const float* du_w     = (const float*)d_in[13];
    const float* du_b     = (const float*)d_in[14];
    const float* term_w   = (const float*)d_in[15];
    const float* term_b   = (const float*)d_in[16];
    float* out = (float*)d_out;

    int N = in_sizes[1];
    int E = in_sizes[3];
    int T = in_sizes[0] / N;
    int Kc = E / N;
    int Erem = E - Kc * N;
    int KS = Kc + (Erem ? 1 : 0);
    int KS8 = (KS + 7) & ~7;          // pad to multiple of 8

    int nb = (N + 15) / 16;           // 625 for N=10000; all resident (<=740)
    k_all<<<nb, 256>>>(states, priority, edges, src, enc_w, enc_b, M_w, M_b,
                       U_w, U_b, dn_w, dn_b, du_w, du_b,
                       term_w, term_b, out, N, T, KS8, Kc, Erem);
}

// round 17
// speedup vs baseline: 1.5605x; 1.5605x over previous
#include <cuda_runtime.h>
#include <math.h>

#define HID 32
#define MAXN 10240
#define MAXSEF 1100000

// device scratch (no allocs allowed)
__device__ __align__(16) float g_A[2][MAXN * HID];  // z @ M_w[0:32], dbl-buffered
__device__ __align__(16) int2 g_pair[MAXSEF];       // (src, ef bits) [n][k], padded
__device__ float g_blockmax[8 * 1024];
__device__ volatile unsigned g_gen;                 // barrier generation
__device__ unsigned g_cnt;                          // barrier arrival count

// ---------------------------------------------------------------------------
// Software grid barrier (all blocks resident by construction).
// ---------------------------------------------------------------------------
__device__ __forceinline__ void grid_sync_dev() {
    __threadfence();
    __syncthreads();
    if (threadIdx.x == 0) {
        unsigned gen = g_gen;
        if (atomicAdd(&g_cnt, 1u) == gridDim.x - 1u) {
            g_cnt = 0u;
            __threadfence();
            g_gen = gen + 1u;
        } else {
            while (g_gen == gen) __nanosleep(32);
        }
    }
    __syncthreads();
}

// ---------------------------------------------------------------------------
// Persistent fused kernel: init + all T-1 steps + finalize. 8 warps,
// 2 nodes/warp, 16 nodes/block, grid ceil(N/16) (all resident: lb(256,5)).
// Step 0 gathers edge features from edges_mat on the fly (MLP-2) and caches
// (src, ef) into g_pair for steps >=1. z and Bc live in registers.
// Node phase uses float2-packed weights + float4 operand staging.
// ---------------------------------------------------------------------------
__global__ void __launch_bounds__(256, 5) k_all(
        const float* __restrict__ states0, const float* __restrict__ pri,
        const float* __restrict__ edges,  const int* __restrict__ src,
        const float* __restrict__ encw, const float* __restrict__ encb,
        const float* __restrict__ Mw,   const float* __restrict__ Mb,
        const float* __restrict__ Uw,   const float* __restrict__ Ub,
        const float* __restrict__ dnw,  const float* __restrict__ dnb,
        const float* __restrict__ duw,  const float* __restrict__ dub,
        const float* __restrict__ termw,const float* __restrict__ termb,
        float* __restrict__ out, int N, int T, int KS8, int Kc, int Erem) {
    __shared__ float  s_encw[34 * HID];
    __shared__ __align__(8)  float2 s_Uw2[HID * HID];   // (Uw[i][j], Uw[32+i][j])
    __shared__ __align__(8)  float2 s_Mw2[HID * HID];   // (Mw[i][j], Mw[32+i][j])
    __shared__ float  s_dnw[64];
    __shared__ float  s_duw[65];
    __shared__ float  s_termw[HID];
    __shared__ __align__(16) float s_um[8][64];
    __shared__ __align__(16) float4 s_zu[HID][9];       // stride 9 -> conflict-free
    __shared__ float  s_red[8];
    __shared__ float  s_fin[256];

    int tid = threadIdx.x;
    for (int i = tid; i < 34 * HID; i += 256) s_encw[i] = encw[i];
    for (int idx = tid; idx < HID * HID; idx += 256) {
        int i = idx >> 5, j2 = idx & 31;
        s_Uw2[idx] = make_float2(Uw[i * HID + j2], Uw[(HID + i) * HID + j2]);
        s_Mw2[idx] = make_float2(Mw[i * HID + j2], Mw[(HID + i) * HID + j2]);
    }
    if (tid < 64) s_dnw[tid] = dnw[tid];
    if (tid < 65) s_duw[tid] = duw[tid];
    if (tid < HID) s_termw[tid] = termw[tid];
    __syncthreads();

    int w = tid >> 5, j = tid & 31;
    int n0 = blockIdx.x * 16 + w * 2;
    bool active = (n0 < N);
    int g = j >> 3, c4 = (j & 7) << 2;      // lane group, col base
    bool gl = ((j & 7) == 0);               // group leader lane
    const float4 fw4 = *(const float4*)(Mw + 64 * HID + c4);

    float z0 = 0.f, z1 = 0.f, bc0 = 0.f, bc1 = 0.f;

    // ---------------- init: z0/A0/Bc0 from states[0], preds[0] --------------
    if (active) {
        const float2 st2 = *(const float2*)(states0 + n0);
        const float2 p2  = *(const float2*)(pri + n0);
        float eb = __ldg(encb + j);
        float ew0 = s_encw[j], ew33 = s_encw[33 * HID + j];
        z0 = fmaf(st2.x, ew0, fmaf(p2.x, ew33, eb));
        z1 = fmaf(st2.y, ew0, fmaf(p2.y, ew33, eb));
        if (j < 2) out[n0 + j] = (j == 0) ? st2.x : st2.y;
        s_zu[j][w] = make_float4(z0, z1, 0.f, 0.f);
        __syncwarp();
        float A0 = 0, A1 = 0, B0 = 0, B1 = 0;
        #pragma unroll
        for (int i = 0; i < HID; i++) {
            float2 m2 = s_Mw2[i * HID + j];
            float4 v = s_zu[i][w];
            A0 = fmaf(v.x, m2.x, A0); B0 = fmaf(v.x, m2.y, B0);
            A1 = fmaf(v.y, m2.x, A1); B1 = fmaf(v.y, m2.y, B1);
        }
        float mb = __ldg(Mb + j);
        int r = n0 * HID + j;
        g_A[0][r] = A0; g_A[0][r + HID] = A1;
        bc0 = B0 + mb; bc1 = B1 + mb;
    }
    grid_sync_dev();

    // ---------------- T-1 fused steps ---------------------------------------
    for (int t = 0; t < T - 1; t++) {
        bool lastStep = (t == T - 2);
        float locmax = -INFINITY;

        if (active) {
            const float* __restrict__ Aold = g_A[t & 1];
            #pragma unroll
            for (int qi = 0; qi < 2; qi++) {
                int n = n0 + qi;
                float mx = -INFINITY, my = -INFINITY, mz = -INFINITY, mw2 = -INFINITY;
                if (t == 0) {
                    // fused ef gather: src from L2, edges from DRAM (random),
                    // cache (s, ef) into g_pair for later steps.
                    int kn = Kc + (n < Erem ? 1 : 0);
                    long base = (long)n * KS8;
                    for (int k = 0; k < KS8; k += 8) {
                        int k0 = k + g, k1 = k + 4 + g;
                        int e0 = (k0 < kn) ? k0 * N + n : n;
                        int e1 = (k1 < kn) ? k1 * N + n : n;
                        int s0 = __ldg(src + e0);
                        int s1 = __ldg(src + e1);
                        float f0 = __ldcs(edges + (long)s0 * N + n);
                        float f1 = __ldcs(edges + (long)s1 * N + n);
                        if (gl) {
                            g_pair[base + k0] = make_int2(s0, __float_as_int(f0));
                            g_pair[base + k1] = make_int2(s1, __float_as_int(f1));
                        }
                        float4 a0 = __ldg((const float4*)(Aold + (s0 << 5) + c4));
                        float4 a1 = __ldg((const float4*)(Aold + (s1 << 5) + c4));
                        mx  = fmaxf(mx,  fmaf(f0, fw4.x, a0.x));
                        my  = fmaxf(my,  fmaf(f0, fw4.y, a0.y));
                        mz  = fmaxf(mz,  fmaf(f0, fw4.z, a0.z));
                        mw2 = fmaxf(mw2, fmaf(f0, fw4.w, a0.w));
                        mx  = fmaxf(mx,  fmaf(f1, fw4.x, a1.x));
                        my  = fmaxf(my,  fmaf(f1, fw4.y, a1.y));
                        mz  = fmaxf(mz,  fmaf(f1, fw4.z, a1.z));
                        mw2 = fmaxf(mw2, fmaf(f1, fw4.w, a1.w));
                    }
                } else {
                    const int2* __restrict__ pp = g_pair + (long)n * KS8 + g;
                    for (int k = 0; k < KS8; k += 8) {
                        int2 q0 = __ldg(pp + k);
                        int2 q1 = __ldg(pp + k + 4);
                        float4 a0 = __ldg((const float4*)(Aold + (q0.x << 5) + c4));
                        float4 a1 = __ldg((const float4*)(Aold + (q1.x << 5) + c4));
                        float f0 = __int_as_float(q0.y);
                        float f1 = __int_as_float(q1.y);
                        mx  = fmaxf(mx,  fmaf(f0, fw4.x, a0.x));
                        my  = fmaxf(my,  fmaf(f0, fw4.y, a0.y));
                        mz  = fmaxf(mz,  fmaf(f0, fw4.z, a0.z));
                        mw2 = fmaxf(mw2, fmaf(f0, fw4.w, a0.w));
                        mx  = fmaxf(mx,  fmaf(f1, fw4.x, a1.x));
                        my  = fmaxf(my,  fmaf(f1, fw4.y, a1.y));
                        mz  = fmaxf(mz,  fmaf(f1, fw4.z, a1.z));
                        mw2 = fmaxf(mw2, fmaf(f1, fw4.w, a1.w));
                    }
                }
                mx  = fmaxf(mx,  __shfl_xor_sync(0xffffffffu, mx, 8));
                my  = fmaxf(my,  __shfl_xor_sync(0xffffffffu, my, 8));
                mz  = fmaxf(mz,  __shfl_xor_sync(0xffffffffu, mz, 8));
                mw2 = fmaxf(mw2, __shfl_xor_sync(0xffffffffu, mw2, 8));
                mx  = fmaxf(mx,  __shfl_xor_sync(0xffffffffu, mx, 16));
                my  = fmaxf(my,  __shfl_xor_sync(0xffffffffu, my, 16));
                mz  = fmaxf(mz,  __shfl_xor_sync(0xffffffffu, mz, 16));
                mw2 = fmaxf(mw2, __shfl_xor_sync(0xffffffffu, mw2, 16));
                if (g == 0)
                    *(float4*)&s_um[w][qi * 32 + c4] = make_float4(mx, my, mz, mw2);
            }
            __syncwarp();

            // ---------------- node phase (packed operands) ------------------
            float u0 = bc0 + s_um[w][j];
            float u1 = bc1 + s_um[w][32 + j];
            s_zu[j][w] = make_float4(z0, z1, u0, u1);
            __syncwarp();
            float ub = __ldg(Ub + j);
            float nh0 = ub, nh1 = ub;
            #pragma unroll
            for (int i = 0; i < HID; i++) {
                float2 u2 = s_Uw2[i * HID + j];
                float4 v = s_zu[i][w];
                nh0 = fmaf(v.x, u2.x, nh0); nh0 = fmaf(v.z, u2.y, nh0);
                nh1 = fmaf(v.y, u2.x, nh1); nh1 = fmaf(v.w, u2.y, nh1);
            }
            float tw = s_termw[j], d1 = s_dnw[j], d2 = s_dnw[HID + j];
            float e1 = s_duw[j], e2 = s_duw[HID + j];
            float l0 = nh0 * tw, l1 = nh1 * tw;
            float qd0 = fmaf(nh0, d1, z0 * d2), qd1 = fmaf(nh1, d1, z1 * d2);
            float rd0 = fmaf(nh0, e1, z0 * e2), rd1 = fmaf(nh1, e1, z1 * e2);
            #pragma unroll
            for (int o = 16; o; o >>= 1) {
                l0  += __shfl_xor_sync(0xffffffffu, l0, o);
                l1  += __shfl_xor_sync(0xffffffffu, l1, o);
                qd0 += __shfl_xor_sync(0xffffffffu, qd0, o);
                qd1 += __shfl_xor_sync(0xffffffffu, qd1, o);
                rd0 += __shfl_xor_sync(0xffffffffu, rd0, o);
                rd1 += __shfl_xor_sync(0xffffffffu, rd1, o);
            }
            locmax = fmaxf(l0, l1) + __ldg(termb);
            float db = __ldg(dnb), du0 = __ldg(dub), dw64 = s_duw[64];
            float nn0 = qd0 + db, nn1 = qd1 + db;
            float ns0 = fmaf(nn0, dw64, rd0 + du0);
            float ns1 = fmaf(nn1, dw64, rd1 + du0);
            if (j < 2) {
                float nsv = (j == 0) ? ns0 : ns1;
                float nnv = (j == 0) ? nn0 : nn1;
                out[(t + 1) * N + n0 + j] = nsv;                  // preds
                out[T * N + T + (n0 + j) * (T - 1) + t] = nnv;    // preds_nextnode
            }
            if (!lastStep) {
                s_zu[j][w] = make_float4(nh0, nh1, 0.f, 0.f);
                __syncwarp();
                const float2 p2 = *(const float2*)(pri + n0);
                float eb = __ldg(encb + j);
                float ew0 = s_encw[j], ew33 = s_encw[33 * HID + j];
                float zn0 = fmaf(ns0, ew0, fmaf(p2.x, ew33, eb));
                float zn1 = fmaf(ns1, ew0, fmaf(p2.y, ew33, eb));
                #pragma unroll
                for (int i = 0; i < HID; i++) {
                    float we = s_encw[(1 + i) * HID + j];
                    float4 v = s_zu[i][w];
                    zn0 = fmaf(v.x, we, zn0); zn1 = fmaf(v.y, we, zn1);
                }
                s_zu[j][w] = make_float4(zn0, zn1, 0.f, 0.f);
                __syncwarp();
                float A0 = 0, A1 = 0, B0 = 0, B1 = 0;
                #pragma unroll
                for (int i = 0; i < HID; i++) {
                    float2 m2 = s_Mw2[i * HID + j];
                    float4 v = s_zu[i][w];
                    A0 = fmaf(v.x, m2.x, A0); B0 = fmaf(v.x, m2.y, B0);
                    A1 = fmaf(v.y, m2.x, A1); B1 = fmaf(v.y, m2.y, B1);
                }
                float mb = __ldg(Mb + j);
                float* __restrict__ Anew = g_A[(t & 1) ^ 1];
                int r = n0 * HID + j;
                Anew[r] = A0; Anew[r + HID] = A1;
                z0 = zn0; z1 = zn1;
                bc0 = B0 + mb; bc1 = B1 + mb;
            }
        }

        if (j == 0) s_red[w] = active ? locmax : -INFINITY;
        __syncthreads();
        if (tid == 0) {
            float m = -INFINITY;
            #pragma unroll
            for (int ww = 0; ww < 8; ww++) m = fmaxf(m, s_red[ww]);
            g_blockmax[t * 1024 + blockIdx.x] = m;
        }
        if (!lastStep) grid_sync_dev();
    }

    // ---------------- finalize (folded k_final) -----------------------------
    grid_sync_dev();
    if (blockIdx.x < (unsigned)(T - 1)) {
        int t = blockIdx.x;
        float m = -INFINITY;
        for (int b = tid; b < gridDim.x; b += 256)
            m = fmaxf(m, g_blockmax[t * 1024 + b]);
        s_fin[tid] = m;
        __syncthreads();
        for (int s = 128; s; s >>= 1) {
            if (tid < s) s_fin[tid] = fmaxf(s_fin[tid], s_fin[tid + s]);
            __syncthreads();
        }
        if (tid == 0) {
            float v = s_fin[0];
            out[T * N + 1 + t] = 1.0f / (1.0f + expf(-v));
            if (t == 0) out[T * N] = 0.0f;
        }
    }
}

// ---------------------------------------------------------------------------
extern "C" void kernel_launch(void* const* d_in, const int* in_sizes, int n_in,
                              void* d_out, int out_size) {
    const float* states   = (const float*)d_in[0];
    const float* priority = (const float*)d_in[1];
    const float* edges    = (const float*)d_in[2];
    const int*   src      = (const int*)d_in[3];
    const float* enc_w    = (const float*)d_in[5];
    const float* enc_b    = (const float*)d_in[6];
    const float* M_w      = (const float*)d_in[7];
    const float* M_b      = (const float*)d_in[8];
    const float* U_w      = (const float*)d_in[9];
    const float* U_b      = (const float*)d_in[10];
    const float* dn_w     = (const float*)d_in[11];
    const float* dn_b     = (const float*)d_in[12];
    const float* du_w     = (const float*)d_in[13];
    const float* du_b     = (const float*)d_in[14];
    const float* term_w   = (const float*)d_in[15];
    const float* term_b   = (const float*)d_in[16];
    float* out = (float*)d_out;

    int N = in_sizes[1];
    int E = in_sizes[3];
    int T = in_sizes[0] / N;
    int Kc = E / N;
    int Erem = E - Kc * N;
    int KS = Kc + (Erem ? 1 : 0);
    int KS8 = (KS + 7) & ~7;          // pad to multiple of 8

    int nb = (N + 15) / 16;           // 625 for N=10000; all resident (<=740)
    k_all<<<nb, 256>>>(states, priority, edges, src, enc_w, enc_b, M_w, M_b,
                       U_w, U_b, dn_w, dn_b, du_w, du_b,
                       term_w, term_b, out, N, T, KS8, Kc, Erem);
}